// round 5
// baseline (speedup 1.0000x reference)
#include <cuda_runtime.h>

// Problem dims (InnerAttention): x[B,M,D], y[B,N,D] -> out[B,N,D]
// S[b,m,n] = <x[b,m,:], y[b,n,:]>, P = softmax over n, out[b,n,d] = sum_m P[b,m,n]*x[b,m,d]
#define BATCH 8
#define MDIM  2048
#define NDIM  2048
#define DDIM  1024

// 128 MB scratch for S / P (device global — allocation-free per harness rules)
__device__ float g_P[(size_t)BATCH * MDIM * NDIM];

// ---------------------------------------------------------------------------
// GEMM1 (NT): C[M,N] = A[M,K] * B[N,K]^T   (both K-contiguous, row-major)
// 128x128 CTA tile, BK=8, 256 threads, 8x8 per-thread micro-tile.
// ---------------------------------------------------------------------------
__global__ __launch_bounds__(256, 2)
void gemm_nt_kernel(const float* __restrict__ A, const float* __restrict__ B,
                    float* __restrict__ C, int M, int N, int K)
{
    const int BM = 128, BN = 128, BK = 8;
    __shared__ float As[BK][BM];
    __shared__ float Bs[BK][BN];

    const int b = blockIdx.z;
    const float* Ab = A + (size_t)b * M * K + (size_t)blockIdx.y * BM * K;
    const float* Bb = B + (size_t)b * N * K + (size_t)blockIdx.x * BN * K;
    float*       Cb = C + (size_t)b * M * N + (size_t)blockIdx.y * BM * N + (size_t)blockIdx.x * BN;

    const int tid = threadIdx.x;          // 0..255
    const int a_row = tid >> 1;           // 0..127
    const int a_col = (tid & 1) * 4;      // 0 or 4
    const int m_base = (tid >> 4) * 8;    // 0..120
    const int n_base = (tid & 15) * 8;    // 0..120

    float acc[8][8];
    #pragma unroll
    for (int i = 0; i < 8; i++)
        #pragma unroll
        for (int j = 0; j < 8; j++) acc[i][j] = 0.f;

    for (int k0 = 0; k0 < K; k0 += BK) {
        float4 av = *(const float4*)(Ab + (size_t)a_row * K + k0 + a_col);
        float4 bv = *(const float4*)(Bb + (size_t)a_row * K + k0 + a_col);
        // transpose into k-major smem
        As[a_col + 0][a_row] = av.x; As[a_col + 1][a_row] = av.y;
        As[a_col + 2][a_row] = av.z; As[a_col + 3][a_row] = av.w;
        Bs[a_col + 0][a_row] = bv.x; Bs[a_col + 1][a_row] = bv.y;
        Bs[a_col + 2][a_row] = bv.z; Bs[a_col + 3][a_row] = bv.w;
        __syncthreads();

        #pragma unroll
        for (int k = 0; k < BK; k++) {
            float ar[8], br[8];
            float4 a0 = *(const float4*)&As[k][m_base];
            float4 a1 = *(const float4*)&As[k][m_base + 4];
            float4 b0 = *(const float4*)&Bs[k][n_base];
            float4 b1 = *(const float4*)&Bs[k][n_base + 4];
            ar[0]=a0.x; ar[1]=a0.y; ar[2]=a0.z; ar[3]=a0.w;
            ar[4]=a1.x; ar[5]=a1.y; ar[6]=a1.z; ar[7]=a1.w;
            br[0]=b0.x; br[1]=b0.y; br[2]=b0.z; br[3]=b0.w;
            br[4]=b1.x; br[5]=b1.y; br[6]=b1.z; br[7]=b1.w;
            #pragma unroll
            for (int i = 0; i < 8; i++)
                #pragma unroll
                for (int j = 0; j < 8; j++)
                    acc[i][j] = fmaf(ar[i], br[j], acc[i][j]);
        }
        __syncthreads();
    }

    #pragma unroll
    for (int i = 0; i < 8; i++) {
        float4 c0 = {acc[i][0], acc[i][1], acc[i][2], acc[i][3]};
        float4 c1 = {acc[i][4], acc[i][5], acc[i][6], acc[i][7]};
        *(float4*)(Cb + (size_t)(m_base + i) * N + n_base)     = c0;
        *(float4*)(Cb + (size_t)(m_base + i) * N + n_base + 4) = c1;
    }
}

// ---------------------------------------------------------------------------
// Row softmax in place: one CTA per row of length NDIM (=2048), 256 threads.
// ---------------------------------------------------------------------------
__global__ __launch_bounds__(256)
void softmax_rows_kernel(float* __restrict__ P)
{
    float* p = P + (size_t)blockIdx.x * NDIM;
    const int tid = threadIdx.x;
    const int lane = tid & 31;
    const int wid  = tid >> 5;
    __shared__ float red[8];

    // 2048 = 256 threads * 8 floats: two coalesced float4 chunks
    float4 v0 = *(const float4*)(p + tid * 4);
    float4 v1 = *(const float4*)(p + 1024 + tid * 4);

    float m = fmaxf(fmaxf(fmaxf(v0.x, v0.y), fmaxf(v0.z, v0.w)),
                    fmaxf(fmaxf(v1.x, v1.y), fmaxf(v1.z, v1.w)));
    #pragma unroll
    for (int off = 16; off > 0; off >>= 1)
        m = fmaxf(m, __shfl_xor_sync(0xffffffffu, m, off));
    if (lane == 0) red[wid] = m;
    __syncthreads();
    if (tid == 0) {
        float mm = red[0];
        #pragma unroll
        for (int w = 1; w < 8; w++) mm = fmaxf(mm, red[w]);
        red[0] = mm;
    }
    __syncthreads();
    const float rowmax = red[0];
    __syncthreads();

    v0.x = __expf(v0.x - rowmax); v0.y = __expf(v0.y - rowmax);
    v0.z = __expf(v0.z - rowmax); v0.w = __expf(v0.w - rowmax);
    v1.x = __expf(v1.x - rowmax); v1.y = __expf(v1.y - rowmax);
    v1.z = __expf(v1.z - rowmax); v1.w = __expf(v1.w - rowmax);

    float s = v0.x + v0.y + v0.z + v0.w + v1.x + v1.y + v1.z + v1.w;
    #pragma unroll
    for (int off = 16; off > 0; off >>= 1)
        s += __shfl_xor_sync(0xffffffffu, s, off);
    if (lane == 0) red[wid] = s;
    __syncthreads();
    if (tid == 0) {
        float ss = red[0];
        #pragma unroll
        for (int w = 1; w < 8; w++) ss += red[w];
        red[0] = ss;
    }
    __syncthreads();
    const float scale = 1.0f / red[0];

    v0.x *= scale; v0.y *= scale; v0.z *= scale; v0.w *= scale;
    v1.x *= scale; v1.y *= scale; v1.z *= scale; v1.w *= scale;
    *(float4*)(p + tid * 4) = v0;
    *(float4*)(p + 1024 + tid * 4) = v1;
}

// ---------------------------------------------------------------------------
// GEMM2 (TN): O[N,D] = P^T * X, with P stored [K=M, N], X stored [K=M, D].
// Both smem tiles load naturally in [K][MN] layout (coalesced, no transpose).
// ---------------------------------------------------------------------------
__global__ __launch_bounds__(256, 2)
void gemm_tn_kernel(const float* __restrict__ P, const float* __restrict__ X,
                    float* __restrict__ O, int N, int D, int K)
{
    const int BN = 128, BD = 128, BK = 8;
    __shared__ float Ps[BK][BN];
    __shared__ float Xs[BK][BD];

    const int b = blockIdx.z;
    const float* Pb = P + (size_t)b * K * N + (size_t)blockIdx.y * BN;
    const float* Xb = X + (size_t)b * K * D + (size_t)blockIdx.x * BD;
    float*       Ob = O + (size_t)b * N * D + (size_t)blockIdx.y * BN * D + (size_t)blockIdx.x * BD;

    const int tid = threadIdx.x;
    const int kr  = tid >> 5;          // 0..7
    const int col = (tid & 31) * 4;    // 0..124
    const int n_base = (tid >> 4) * 8;
    const int d_base = (tid & 15) * 8;

    float acc[8][8];
    #pragma unroll
    for (int i = 0; i < 8; i++)
        #pragma unroll
        for (int j = 0; j < 8; j++) acc[i][j] = 0.f;

    for (int k0 = 0; k0 < K; k0 += BK) {
        *(float4*)&Ps[kr][col] = *(const float4*)(Pb + (size_t)(k0 + kr) * N + col);
        *(float4*)&Xs[kr][col] = *(const float4*)(Xb + (size_t)(k0 + kr) * D + col);
        __syncthreads();

        #pragma unroll
        for (int k = 0; k < BK; k++) {
            float ar[8], br[8];
            float4 a0 = *(const float4*)&Ps[k][n_base];
            float4 a1 = *(const float4*)&Ps[k][n_base + 4];
            float4 b0 = *(const float4*)&Xs[k][d_base];
            float4 b1 = *(const float4*)&Xs[k][d_base + 4];
            ar[0]=a0.x; ar[1]=a0.y; ar[2]=a0.z; ar[3]=a0.w;
            ar[4]=a1.x; ar[5]=a1.y; ar[6]=a1.z; ar[7]=a1.w;
            br[0]=b0.x; br[1]=b0.y; br[2]=b0.z; br[3]=b0.w;
            br[4]=b1.x; br[5]=b1.y; br[6]=b1.z; br[7]=b1.w;
            #pragma unroll
            for (int i = 0; i < 8; i++)
                #pragma unroll
                for (int j = 0; j < 8; j++)
                    acc[i][j] = fmaf(ar[i], br[j], acc[i][j]);
        }
        __syncthreads();
    }

    #pragma unroll
    for (int i = 0; i < 8; i++) {
        float4 c0 = {acc[i][0], acc[i][1], acc[i][2], acc[i][3]};
        float4 c1 = {acc[i][4], acc[i][5], acc[i][6], acc[i][7]};
        *(float4*)(Ob + (size_t)(n_base + i) * D + d_base)     = c0;
        *(float4*)(Ob + (size_t)(n_base + i) * D + d_base + 4) = c1;
    }
}

// ---------------------------------------------------------------------------
extern "C" void kernel_launch(void* const* d_in, const int* in_sizes, int n_in,
                              void* d_out, int out_size)
{
    const float* x = (const float*)d_in[0];   // [B, M, D]
    const float* y = (const float*)d_in[1];   // [B, N, D]
    float* out = (float*)d_out;               // [B, N, D]

    float* Pg = nullptr;
    cudaGetSymbolAddress((void**)&Pg, g_P);

    // GEMM1: S[b] = X[b] * Y[b]^T  -> g_P
    {
        dim3 grid(NDIM / 128, MDIM / 128, BATCH);
        gemm_nt_kernel<<<grid, 256>>>(x, y, Pg, MDIM, NDIM, DDIM);
    }
    // Softmax rows of S in place -> P
    {
        softmax_rows_kernel<<<BATCH * MDIM, 256>>>(Pg);
    }
    // GEMM2: O[b] = P[b]^T * X[b]
    {
        dim3 grid(DDIM / 128, NDIM / 128, BATCH);
        gemm_tn_kernel<<<grid, 256>>>(Pg, x, out, NDIM, DDIM, MDIM);
    }
}

// round 9
// speedup vs baseline: 2.2561x; 2.2561x over previous
#include <cuda_runtime.h>
#include <cuda_bf16.h>
#include <cstdint>

#define BATCH 8
#define MDIM  2048
#define NDIM  2048
#define DDIM  1024

// ---------------- device scratch ----------------
__device__ float         g_St  [(size_t)BATCH * NDIM * MDIM];   // St[b][n][m] fp32
__device__ __nv_bfloat16 g_xh  [(size_t)BATCH * MDIM * DDIM];
__device__ __nv_bfloat16 g_xl  [(size_t)BATCH * MDIM * DDIM];
__device__ __nv_bfloat16 g_yh  [(size_t)BATCH * NDIM * DDIM];
__device__ __nv_bfloat16 g_yl  [(size_t)BATCH * NDIM * DDIM];
__device__ __nv_bfloat16 g_Eth [(size_t)BATCH * NDIM * MDIM];
__device__ __nv_bfloat16 g_Etl [(size_t)BATCH * NDIM * MDIM];
__device__ __nv_bfloat16 g_xsth[(size_t)BATCH * DDIM * MDIM];   // (x/s)^T [b][d][m]
__device__ __nv_bfloat16 g_xstl[(size_t)BATCH * DDIM * MDIM];
__device__ unsigned      g_cmax[BATCH * MDIM];
__device__ float         g_sum [BATCH * MDIM];

// ---------------- helpers ----------------
__device__ __forceinline__ uint32_t smem_u32(const void* p) {
    return (uint32_t)__cvta_generic_to_shared(p);
}
__device__ __forceinline__ void cp16(uint32_t s, const void* g) {
    asm volatile("cp.async.cg.shared.global [%0], [%1], 16;" :: "r"(s), "l"(g));
}
__device__ __forceinline__ void mma16816(float* c, const uint32_t* a, const uint32_t* b) {
    asm volatile(
        "mma.sync.aligned.m16n8k16.row.col.f32.bf16.bf16.f32 "
        "{%0,%1,%2,%3}, {%4,%5,%6,%7}, {%8,%9}, {%0,%1,%2,%3};"
        : "+f"(c[0]), "+f"(c[1]), "+f"(c[2]), "+f"(c[3])
        : "r"(a[0]), "r"(a[1]), "r"(a[2]), "r"(a[3]), "r"(b[0]), "r"(b[1]));
}
// monotone float<->uint encoding for atomicMax
__device__ __forceinline__ unsigned fenc(float f) {
    unsigned u = __float_as_uint(f);
    return (u & 0x80000000u) ? ~u : (u | 0x80000000u);
}
__device__ __forceinline__ float fdec(unsigned u) {
    return __uint_as_float((u & 0x80000000u) ? (u ^ 0x80000000u) : ~u);
}

// ---------------- GEMM (mma.sync bf16 x3 split) ----------------
// C[i][j] = sum_k A[i][k]*B[j][k]; A tile 128 rows (blockIdx.y), B tile 128 rows
// (blockIdx.x). BK=32. smem rows padded to 40 halves (80B) -> conflict-free
// per-lane LDS.32 fragment loads (bank = (20r + c) mod 32, distinct per group).
#define BK     32
#define LDA    40                         // halves per smem row
#define TILE_H (128 * LDA)                // halves per tile (5120)
#define STG_H  (4 * TILE_H)               // halves per stage (Ah,Al,Bh,Bl) = 20480
#define GEMM_SMEM (2 * STG_H * 2)         // bytes (81920)

__device__ __forceinline__ void ldtile(const __nv_bfloat16* gp, int K, int k0,
                                       uint32_t sb, int tid)
{
    #pragma unroll
    for (int i = 0; i < 2; i++) {
        int s = i * 256 + tid;            // 0..511
        int row = s >> 2, c = s & 3;      // 4 x 16B per 64B row
        cp16(sb + (uint32_t)(row * 80 + c * 16),
             (const char*)(gp + (size_t)row * K + k0) + c * 16);
    }
}

__global__ void __launch_bounds__(256, 1)
gemm_bf16x3(const __nv_bfloat16* __restrict__ Ah, const __nv_bfloat16* __restrict__ Al,
            const __nv_bfloat16* __restrict__ Bh, const __nv_bfloat16* __restrict__ Bl,
            float* __restrict__ C,
            int K, size_t sAb, size_t sBb, size_t sCb, int ldC)
{
    extern __shared__ __nv_bfloat16 sm[];
    const int tid  = threadIdx.x;
    const int warp = tid >> 5, lane = tid & 31;
    const int g = lane >> 2, tg = lane & 3;
    const int wr = warp >> 2;            // 0..1  -> m offset 0/64
    const int wc = warp & 3;             // 0..3  -> n offset 0/32/64/96
    const int m_w = wr * 64;
    const int n_w = wc * 32;

    const int b  = blockIdx.z;
    const int i0 = blockIdx.y * 128;
    const int j0 = blockIdx.x * 128;

    const __nv_bfloat16* ah = Ah + (size_t)b * sAb + (size_t)i0 * K;
    const __nv_bfloat16* al = Al + (size_t)b * sAb + (size_t)i0 * K;
    const __nv_bfloat16* bh = Bh + (size_t)b * sBb + (size_t)j0 * K;
    const __nv_bfloat16* bl = Bl + (size_t)b * sBb + (size_t)j0 * K;

    const uint32_t sb0 = smem_u32(sm);
    const uint32_t* sw = (const uint32_t*)sm;    // word view of smem

    float acc[4][4][4];
    #pragma unroll
    for (int i = 0; i < 4; i++)
        #pragma unroll
        for (int j = 0; j < 4; j++)
            #pragma unroll
            for (int q = 0; q < 4; q++) acc[i][j][q] = 0.f;

    const int NT = K / BK;

    // prologue: stage 0
    {
        uint32_t sb = sb0;
        ldtile(ah, K, 0, sb + 0 * TILE_H * 2, tid);
        ldtile(al, K, 0, sb + 1 * TILE_H * 2, tid);
        ldtile(bh, K, 0, sb + 2 * TILE_H * 2, tid);
        ldtile(bl, K, 0, sb + 3 * TILE_H * 2, tid);
        asm volatile("cp.async.commit_group;" ::: "memory");
    }

    for (int kt = 0; kt < NT; kt++) {
        if (kt + 1 < NT) {
            uint32_t sb = sb0 + (uint32_t)(((kt + 1) & 1) * STG_H * 2);
            int k0 = (kt + 1) * BK;
            ldtile(ah, K, k0, sb + 0 * TILE_H * 2, tid);
            ldtile(al, K, k0, sb + 1 * TILE_H * 2, tid);
            ldtile(bh, K, k0, sb + 2 * TILE_H * 2, tid);
            ldtile(bl, K, k0, sb + 3 * TILE_H * 2, tid);
            asm volatile("cp.async.commit_group;" ::: "memory");
            asm volatile("cp.async.wait_group 1;" ::: "memory");
        } else {
            asm volatile("cp.async.wait_group 0;" ::: "memory");
        }
        __syncthreads();

        const int st = (kt & 1) * STG_H;          // halves
        const int aH = st;                         // Ah tile base (halves)
        const int aL = st + TILE_H;
        const int bH = st + 2 * TILE_H;
        const int bL = st + 3 * TILE_H;

        #pragma unroll
        for (int ks = 0; ks < 2; ks++) {
            const int kc = ks * 16 + tg * 2;      // half index of frag pair
            // load fragments
            uint32_t fah[4][4], fal[4][4], fbh[4][2], fbl[4][2];
            #pragma unroll
            for (int i = 0; i < 4; i++) {
                int r0 = m_w + i * 16 + g;
                fah[i][0] = sw[(aH + r0 * LDA + kc) >> 1];
                fah[i][1] = sw[(aH + (r0 + 8) * LDA + kc) >> 1];
                fah[i][2] = sw[(aH + r0 * LDA + kc + 8) >> 1];
                fah[i][3] = sw[(aH + (r0 + 8) * LDA + kc + 8) >> 1];
                fal[i][0] = sw[(aL + r0 * LDA + kc) >> 1];
                fal[i][1] = sw[(aL + (r0 + 8) * LDA + kc) >> 1];
                fal[i][2] = sw[(aL + r0 * LDA + kc + 8) >> 1];
                fal[i][3] = sw[(aL + (r0 + 8) * LDA + kc + 8) >> 1];
            }
            #pragma unroll
            for (int j = 0; j < 4; j++) {
                int n0 = n_w + j * 8 + g;
                fbh[j][0] = sw[(bH + n0 * LDA + kc) >> 1];
                fbh[j][1] = sw[(bH + n0 * LDA + kc + 8) >> 1];
                fbl[j][0] = sw[(bL + n0 * LDA + kc) >> 1];
                fbl[j][1] = sw[(bL + n0 * LDA + kc + 8) >> 1];
            }
            // 3-product accumulation
            #pragma unroll
            for (int i = 0; i < 4; i++)
                #pragma unroll
                for (int j = 0; j < 4; j++) {
                    mma16816(acc[i][j], fah[i], fbh[j]);
                    mma16816(acc[i][j], fah[i], fbl[j]);
                    mma16816(acc[i][j], fal[i], fbh[j]);
                }
        }
        __syncthreads();
    }

    // epilogue
    float* Cb = C + (size_t)b * sCb;
    #pragma unroll
    for (int i = 0; i < 4; i++) {
        int r0 = i0 + m_w + i * 16 + g;
        #pragma unroll
        for (int j = 0; j < 4; j++) {
            int c0 = j0 + n_w + j * 8 + tg * 2;
            float2 v0 = {acc[i][j][0], acc[i][j][1]};
            float2 v1 = {acc[i][j][2], acc[i][j][3]};
            *(float2*)(Cb + (size_t)r0 * ldC + c0)       = v0;
            *(float2*)(Cb + (size_t)(r0 + 8) * ldC + c0) = v1;
        }
    }
}

// ---------------- aux kernels ----------------
__global__ void __launch_bounds__(256)
init_stats_kernel()
{
    int i = blockIdx.x * 256 + threadIdx.x;
    if (i < BATCH * MDIM) { g_cmax[i] = 0u; g_sum[i] = 0.f; }
}

__global__ void __launch_bounds__(256)
split_kernel(const float* __restrict__ in, __nv_bfloat16* __restrict__ h,
             __nv_bfloat16* __restrict__ l)
{
    size_t i = ((size_t)blockIdx.x * 256 + threadIdx.x) * 4;
    float4 v = *(const float4*)(in + i);
    __nv_bfloat16 h0 = __float2bfloat16(v.x), h1 = __float2bfloat16(v.y);
    __nv_bfloat16 h2 = __float2bfloat16(v.z), h3 = __float2bfloat16(v.w);
    __nv_bfloat16 l0 = __float2bfloat16(v.x - __bfloat162float(h0));
    __nv_bfloat16 l1 = __float2bfloat16(v.y - __bfloat162float(h1));
    __nv_bfloat16 l2 = __float2bfloat16(v.z - __bfloat162float(h2));
    __nv_bfloat16 l3 = __float2bfloat16(v.w - __bfloat162float(h3));
    __nv_bfloat162* hp = (__nv_bfloat162*)(h + i);
    __nv_bfloat162* lp = (__nv_bfloat162*)(l + i);
    hp[0] = __nv_bfloat162(h0, h1); hp[1] = __nv_bfloat162(h2, h3);
    lp[0] = __nv_bfloat162(l0, l1); lp[1] = __nv_bfloat162(l2, l3);
}

// column (over n) max of St, coalesced along m
__global__ void __launch_bounds__(256)
colmax_kernel()
{
    const int b  = blockIdx.z;
    const int m  = blockIdx.x * 256 + threadIdx.x;
    const int n0 = blockIdx.y * 128;
    const float* p = g_St + ((size_t)b * NDIM + n0) * MDIM + m;
    unsigned best = 0u;
    #pragma unroll 4
    for (int i = 0; i < 128; i++) {
        unsigned e = fenc(p[(size_t)i * MDIM]);
        best = best > e ? best : e;
    }
    atomicMax(&g_cmax[b * MDIM + m], best);
}

// Et = exp(St - colmax) split to bf16 hi/lo; partial column sums
__global__ void __launch_bounds__(256)
exp_kernel()
{
    const int b  = blockIdx.z;
    const int m  = blockIdx.x * 256 + threadIdx.x;
    const int n0 = blockIdx.y * 128;
    const float mx = fdec(g_cmax[b * MDIM + m]);
    const size_t base = ((size_t)b * NDIM + n0) * MDIM + m;
    float s = 0.f;
    #pragma unroll 4
    for (int i = 0; i < 128; i++) {
        size_t idx = base + (size_t)i * MDIM;
        float e = __expf(g_St[idx] - mx);
        s += e;
        __nv_bfloat16 h = __float2bfloat16(e);
        __nv_bfloat16 l = __float2bfloat16(e - __bfloat162float(h));
        g_Eth[idx] = h;
        g_Etl[idx] = l;
    }
    atomicAdd(&g_sum[b * MDIM + m], s);
}

// xst[b][d][m] = x[b][m][d] / sum[b][m], split to bf16 hi/lo (32x32 transpose)
__global__ void __launch_bounds__(256)
xst_kernel(const float* __restrict__ x)
{
    __shared__ float t[32][33];
    __shared__ float sinv[32];
    const int b  = blockIdx.z;
    const int d0 = blockIdx.x * 32;
    const int m0 = blockIdx.y * 32;
    const int tx = threadIdx.x & 31, ty = threadIdx.x >> 5;

    #pragma unroll
    for (int r = ty; r < 32; r += 8)
        t[r][tx] = x[((size_t)b * MDIM + (m0 + r)) * DDIM + d0 + tx];
    if (ty == 0) sinv[tx] = 1.0f / g_sum[b * MDIM + m0 + tx];
    __syncthreads();

    #pragma unroll
    for (int r = ty; r < 32; r += 8) {
        float v = t[tx][r] * sinv[tx];
        __nv_bfloat16 h = __float2bfloat16(v);
        __nv_bfloat16 l = __float2bfloat16(v - __bfloat162float(h));
        size_t o = ((size_t)b * DDIM + (d0 + r)) * MDIM + m0 + tx;
        g_xsth[o] = h;
        g_xstl[o] = l;
    }
}

// ---------------- host ----------------
extern "C" void kernel_launch(void* const* d_in, const int* in_sizes, int n_in,
                              void* d_out, int out_size)
{
    const float* x = (const float*)d_in[0];   // [B,M,D]
    const float* y = (const float*)d_in[1];   // [B,N,D]
    float* out = (float*)d_out;               // [B,N,D]

    cudaFuncSetAttribute(gemm_bf16x3,
                         cudaFuncAttributeMaxDynamicSharedMemorySize, GEMM_SMEM);

    float* St;
    __nv_bfloat16 *xh, *xl, *yh, *yl, *Eth, *Etl, *xsth, *xstl;
    cudaGetSymbolAddress((void**)&St,   g_St);
    cudaGetSymbolAddress((void**)&xh,   g_xh);
    cudaGetSymbolAddress((void**)&xl,   g_xl);
    cudaGetSymbolAddress((void**)&yh,   g_yh);
    cudaGetSymbolAddress((void**)&yl,   g_yl);
    cudaGetSymbolAddress((void**)&Eth,  g_Eth);
    cudaGetSymbolAddress((void**)&Etl,  g_Etl);
    cudaGetSymbolAddress((void**)&xsth, g_xsth);
    cudaGetSymbolAddress((void**)&xstl, g_xstl);

    init_stats_kernel<<<(BATCH * MDIM + 255) / 256, 256>>>();

    const size_t nx = (size_t)BATCH * MDIM * DDIM;   // 16.7M elems each of x,y
    split_kernel<<<(unsigned)(nx / 1024), 256>>>(x, xh, xl);
    split_kernel<<<(unsigned)(nx / 1024), 256>>>(y, yh, yl);

    // GEMM1: St[n][m] = sum_d y[n,d]*x[m,d]; A=y rows n, B=x rows m, K=D
    {
        dim3 grid(MDIM / 128, NDIM / 128, BATCH);
        gemm_bf16x3<<<grid, 256, GEMM_SMEM>>>(
            yh, yl, xh, xl, St,
            DDIM, (size_t)NDIM * DDIM, (size_t)MDIM * DDIM,
            (size_t)NDIM * MDIM, MDIM);
    }
    {
        dim3 grid(MDIM / 256, NDIM / 128, BATCH);
        colmax_kernel<<<grid, 256>>>();
        exp_kernel<<<grid, 256>>>();
    }
    xst_kernel<<<dim3(DDIM / 32, MDIM / 32, BATCH), 256>>>(x);

    // GEMM2: out[n][d] = sum_m Et[n,m]*xst[d,m]; A=Et rows n, B=xst rows d, K=M
    {
        dim3 grid(DDIM / 128, NDIM / 128, BATCH);
        gemm_bf16x3<<<grid, 256, GEMM_SMEM>>>(
            Eth, Etl, xsth, xstl, out,
            MDIM, (size_t)NDIM * MDIM, (size_t)DDIM * MDIM,
            (size_t)NDIM * DDIM, DDIM);
    }
}

// round 10
// speedup vs baseline: 2.6766x; 1.1864x over previous
#include <cuda_runtime.h>
#include <cuda_bf16.h>
#include <cstdint>

#define BATCH 8
#define MDIM  2048
#define NDIM  2048
#define DDIM  1024

// ---------------- device scratch ----------------
__device__ float         g_St  [(size_t)BATCH * NDIM * MDIM];   // St[b][n][m] fp32
__device__ __nv_bfloat16 g_xh  [(size_t)BATCH * MDIM * DDIM];
__device__ __nv_bfloat16 g_xl  [(size_t)BATCH * MDIM * DDIM];
__device__ __nv_bfloat16 g_yh  [(size_t)BATCH * NDIM * DDIM];
__device__ __nv_bfloat16 g_yl  [(size_t)BATCH * NDIM * DDIM];
__device__ __nv_bfloat16 g_Eth [(size_t)BATCH * NDIM * MDIM];
__device__ __nv_bfloat16 g_Etl [(size_t)BATCH * NDIM * MDIM];
__device__ __nv_bfloat16 g_xsth[(size_t)BATCH * DDIM * MDIM];   // (x/s)^T [b][d][m]
__device__ __nv_bfloat16 g_xstl[(size_t)BATCH * DDIM * MDIM];
__device__ unsigned      g_cmax[BATCH * MDIM];
__device__ float         g_sum [BATCH * MDIM];

// ---------------- helpers ----------------
__device__ __forceinline__ uint32_t smem_u32(const void* p) {
    return (uint32_t)__cvta_generic_to_shared(p);
}
__device__ __forceinline__ void cp16(uint32_t s, const void* g) {
    asm volatile("cp.async.cg.shared.global [%0], [%1], 16;" :: "r"(s), "l"(g));
}
__device__ __forceinline__ void mma16816(float* c, const uint32_t* a, const uint32_t* b) {
    asm volatile(
        "mma.sync.aligned.m16n8k16.row.col.f32.bf16.bf16.f32 "
        "{%0,%1,%2,%3}, {%4,%5,%6,%7}, {%8,%9}, {%0,%1,%2,%3};"
        : "+f"(c[0]), "+f"(c[1]), "+f"(c[2]), "+f"(c[3])
        : "r"(a[0]), "r"(a[1]), "r"(a[2]), "r"(a[3]), "r"(b[0]), "r"(b[1]));
}
#define LDM4(r0, r1, r2, r3, addr) \
    asm volatile("ldmatrix.sync.aligned.m8n8.x4.shared.b16 {%0,%1,%2,%3}, [%4];" \
                 : "=r"(r0), "=r"(r1), "=r"(r2), "=r"(r3) : "r"(addr))

// monotone float<->uint encoding for atomicMax
__device__ __forceinline__ unsigned fenc(float f) {
    unsigned u = __float_as_uint(f);
    return (u & 0x80000000u) ? ~u : (u | 0x80000000u);
}
__device__ __forceinline__ float fdec(unsigned u) {
    return __uint_as_float((u & 0x80000000u) ? (u ^ 0x80000000u) : ~u);
}

// ---------------- GEMM (mma.sync bf16 x3 split, ldmatrix frags) ----------------
// C[i][j] = sum_k A[i][k]*B[j][k]; A tile 128 rows (blockIdx.y), B tile 128 rows
// (blockIdx.x). BK=32. smem rows padded to 40 halves (80B): ldmatrix phase
// addresses land on distinct banks (20*r mod 32 distinct over 8 rows).
#define BK     32
#define LDA    40                         // halves per smem row
#define TILE_H (128 * LDA)                // halves per tile (5120)
#define STG_H  (4 * TILE_H)               // halves per stage (Ah,Al,Bh,Bl)
#define GEMM_SMEM (2 * STG_H * 2)         // bytes (81920)

__device__ __forceinline__ void ldtile(const __nv_bfloat16* gp, int K, int k0,
                                       uint32_t sb, int tid)
{
    #pragma unroll
    for (int i = 0; i < 2; i++) {
        int s = i * 256 + tid;            // 0..511
        int row = s >> 2, c = s & 3;      // 4 x 16B per 64B row
        cp16(sb + (uint32_t)(row * 80 + c * 16),
             (const char*)(gp + (size_t)row * K + k0) + c * 16);
    }
}

__global__ void __launch_bounds__(256, 2)
gemm_bf16x3(const __nv_bfloat16* __restrict__ Ah, const __nv_bfloat16* __restrict__ Al,
            const __nv_bfloat16* __restrict__ Bh, const __nv_bfloat16* __restrict__ Bl,
            float* __restrict__ C,
            int K, size_t sAb, size_t sBb, size_t sCb, int ldC)
{
    extern __shared__ __nv_bfloat16 sm[];
    const int tid  = threadIdx.x;
    const int warp = tid >> 5, lane = tid & 31;
    const int g = lane >> 2, tg = lane & 3;
    const int m_w = (warp >> 2) * 64;    // 0/64
    const int n_w = (warp & 3) * 32;     // 0/32/64/96

    const int b  = blockIdx.z;
    const int i0 = blockIdx.y * 128;
    const int j0 = blockIdx.x * 128;

    const __nv_bfloat16* ah = Ah + (size_t)b * sAb + (size_t)i0 * K;
    const __nv_bfloat16* al = Al + (size_t)b * sAb + (size_t)i0 * K;
    const __nv_bfloat16* bh = Bh + (size_t)b * sBb + (size_t)j0 * K;
    const __nv_bfloat16* bl = Bl + (size_t)b * sBb + (size_t)j0 * K;

    const uint32_t sb0 = smem_u32(sm);

    // ldmatrix per-lane source offsets (bytes within a tile)
    const int p  = lane >> 3;            // piece 0..3
    const int rr = lane & 7;
    // A x4: pieces {(m,k0),(m+8,k0),(m,k8),(m+8,k8)}
    const uint32_t aoff = (uint32_t)(((m_w + (p & 1) * 8 + rr) * LDA + (p >> 1) * 8) * 2);
    // B x4: pieces {(j,k0),(j,k8),(j+1,k0),(j+1,k8)}  (jsel = lane>>4)
    const uint32_t boff = (uint32_t)(((n_w + ((lane >> 4) & 1) * 8 + rr) * LDA
                                      + ((lane >> 3) & 1) * 8) * 2);

    float acc[4][4][4];
    #pragma unroll
    for (int i = 0; i < 4; i++)
        #pragma unroll
        for (int j = 0; j < 4; j++)
            #pragma unroll
            for (int q = 0; q < 4; q++) acc[i][j][q] = 0.f;

    const int NT = K / BK;

    // prologue: stage 0
    {
        ldtile(ah, K, 0, sb0 + 0 * TILE_H * 2, tid);
        ldtile(al, K, 0, sb0 + 1 * TILE_H * 2, tid);
        ldtile(bh, K, 0, sb0 + 2 * TILE_H * 2, tid);
        ldtile(bl, K, 0, sb0 + 3 * TILE_H * 2, tid);
        asm volatile("cp.async.commit_group;" ::: "memory");
    }

    for (int kt = 0; kt < NT; kt++) {
        if (kt + 1 < NT) {
            uint32_t sb = sb0 + (uint32_t)(((kt + 1) & 1) * STG_H * 2);
            int k0 = (kt + 1) * BK;
            ldtile(ah, K, k0, sb + 0 * TILE_H * 2, tid);
            ldtile(al, K, k0, sb + 1 * TILE_H * 2, tid);
            ldtile(bh, K, k0, sb + 2 * TILE_H * 2, tid);
            ldtile(bl, K, k0, sb + 3 * TILE_H * 2, tid);
            asm volatile("cp.async.commit_group;" ::: "memory");
            asm volatile("cp.async.wait_group 1;" ::: "memory");
        } else {
            asm volatile("cp.async.wait_group 0;" ::: "memory");
        }
        __syncthreads();

        const uint32_t st  = sb0 + (uint32_t)((kt & 1) * STG_H * 2);
        const uint32_t aHb = st;
        const uint32_t aLb = st + TILE_H * 2;
        const uint32_t bHb = st + 2 * TILE_H * 2;
        const uint32_t bLb = st + 3 * TILE_H * 2;

        #pragma unroll
        for (int ks = 0; ks < 2; ks++) {
            const uint32_t kadd = (uint32_t)(ks * 16 * 2);
            uint32_t fbh[4][2], fbl[4][2];
            LDM4(fbh[0][0], fbh[0][1], fbh[1][0], fbh[1][1], bHb + boff + kadd);
            LDM4(fbh[2][0], fbh[2][1], fbh[3][0], fbh[3][1],
                 bHb + boff + kadd + 16 * LDA * 2);
            LDM4(fbl[0][0], fbl[0][1], fbl[1][0], fbl[1][1], bLb + boff + kadd);
            LDM4(fbl[2][0], fbl[2][1], fbl[3][0], fbl[3][1],
                 bLb + boff + kadd + 16 * LDA * 2);

            #pragma unroll
            for (int i = 0; i < 4; i++) {
                const uint32_t iadd = (uint32_t)(i * 16 * LDA * 2) + kadd;
                uint32_t fa[4], fl[4];
                LDM4(fa[0], fa[1], fa[2], fa[3], aHb + aoff + iadd);
                LDM4(fl[0], fl[1], fl[2], fl[3], aLb + aoff + iadd);
                #pragma unroll
                for (int j = 0; j < 4; j++) {
                    mma16816(acc[i][j], fa, fbh[j]);
                    mma16816(acc[i][j], fa, fbl[j]);
                    mma16816(acc[i][j], fl, fbh[j]);
                }
            }
        }
        __syncthreads();
    }

    // epilogue
    float* Cb = C + (size_t)b * sCb;
    #pragma unroll
    for (int i = 0; i < 4; i++) {
        int r0 = i0 + m_w + i * 16 + g;
        #pragma unroll
        for (int j = 0; j < 4; j++) {
            int c0 = j0 + n_w + j * 8 + tg * 2;
            float2 v0 = {acc[i][j][0], acc[i][j][1]};
            float2 v1 = {acc[i][j][2], acc[i][j][3]};
            *(float2*)(Cb + (size_t)r0 * ldC + c0)       = v0;
            *(float2*)(Cb + (size_t)(r0 + 8) * ldC + c0) = v1;
        }
    }
}

// ---------------- aux kernels ----------------
__global__ void __launch_bounds__(256)
init_stats_kernel()
{
    int i = blockIdx.x * 256 + threadIdx.x;
    if (i < BATCH * MDIM) { g_cmax[i] = 0u; g_sum[i] = 0.f; }
}

__global__ void __launch_bounds__(256)
split_kernel(const float* __restrict__ in, __nv_bfloat16* __restrict__ h,
             __nv_bfloat16* __restrict__ l)
{
    size_t i = ((size_t)blockIdx.x * 256 + threadIdx.x) * 4;
    float4 v = *(const float4*)(in + i);
    __nv_bfloat16 h0 = __float2bfloat16(v.x), h1 = __float2bfloat16(v.y);
    __nv_bfloat16 h2 = __float2bfloat16(v.z), h3 = __float2bfloat16(v.w);
    __nv_bfloat16 l0 = __float2bfloat16(v.x - __bfloat162float(h0));
    __nv_bfloat16 l1 = __float2bfloat16(v.y - __bfloat162float(h1));
    __nv_bfloat16 l2 = __float2bfloat16(v.z - __bfloat162float(h2));
    __nv_bfloat16 l3 = __float2bfloat16(v.w - __bfloat162float(h3));
    __nv_bfloat162* hp = (__nv_bfloat162*)(h + i);
    __nv_bfloat162* lp = (__nv_bfloat162*)(l + i);
    hp[0] = __nv_bfloat162(h0, h1); hp[1] = __nv_bfloat162(h2, h3);
    lp[0] = __nv_bfloat162(l0, l1); lp[1] = __nv_bfloat162(l2, l3);
}

// column (over n) max of St, coalesced along m
__global__ void __launch_bounds__(256)
colmax_kernel()
{
    const int b  = blockIdx.z;
    const int m  = blockIdx.x * 256 + threadIdx.x;
    const int n0 = blockIdx.y * 128;
    const float* p = g_St + ((size_t)b * NDIM + n0) * MDIM + m;
    unsigned best = 0u;
    #pragma unroll 4
    for (int i = 0; i < 128; i++) {
        unsigned e = fenc(p[(size_t)i * MDIM]);
        best = best > e ? best : e;
    }
    atomicMax(&g_cmax[b * MDIM + m], best);
}

// Et = exp(St - colmax) split to bf16 hi/lo; partial column sums
__global__ void __launch_bounds__(256)
exp_kernel()
{
    const int b  = blockIdx.z;
    const int m  = blockIdx.x * 256 + threadIdx.x;
    const int n0 = blockIdx.y * 128;
    const float mx = fdec(g_cmax[b * MDIM + m]);
    const size_t base = ((size_t)b * NDIM + n0) * MDIM + m;
    float s = 0.f;
    #pragma unroll 4
    for (int i = 0; i < 128; i++) {
        size_t idx = base + (size_t)i * MDIM;
        float e = __expf(g_St[idx] - mx);
        s += e;
        __nv_bfloat16 h = __float2bfloat16(e);
        __nv_bfloat16 l = __float2bfloat16(e - __bfloat162float(h));
        g_Eth[idx] = h;
        g_Etl[idx] = l;
    }
    atomicAdd(&g_sum[b * MDIM + m], s);
}

// xst[b][d][m] = x[b][m][d] / sum[b][m], split to bf16 hi/lo (32x32 transpose)
__global__ void __launch_bounds__(256)
xst_kernel(const float* __restrict__ x)
{
    __shared__ float t[32][33];
    __shared__ float sinv[32];
    const int b  = blockIdx.z;
    const int d0 = blockIdx.x * 32;
    const int m0 = blockIdx.y * 32;
    const int tx = threadIdx.x & 31, ty = threadIdx.x >> 5;

    #pragma unroll
    for (int r = ty; r < 32; r += 8)
        t[r][tx] = x[((size_t)b * MDIM + (m0 + r)) * DDIM + d0 + tx];
    if (ty == 0) sinv[tx] = 1.0f / g_sum[b * MDIM + m0 + tx];
    __syncthreads();

    #pragma unroll
    for (int r = ty; r < 32; r += 8) {
        float v = t[tx][r] * sinv[tx];
        __nv_bfloat16 h = __float2bfloat16(v);
        __nv_bfloat16 l = __float2bfloat16(v - __bfloat162float(h));
        size_t o = ((size_t)b * DDIM + (d0 + r)) * MDIM + m0 + tx;
        g_xsth[o] = h;
        g_xstl[o] = l;
    }
}

// ---------------- host ----------------
extern "C" void kernel_launch(void* const* d_in, const int* in_sizes, int n_in,
                              void* d_out, int out_size)
{
    const float* x = (const float*)d_in[0];   // [B,M,D]
    const float* y = (const float*)d_in[1];   // [B,N,D]
    float* out = (float*)d_out;               // [B,N,D]

    cudaFuncSetAttribute(gemm_bf16x3,
                         cudaFuncAttributeMaxDynamicSharedMemorySize, GEMM_SMEM);

    float* St;
    __nv_bfloat16 *xh, *xl, *yh, *yl, *Eth, *Etl, *xsth, *xstl;
    cudaGetSymbolAddress((void**)&St,   g_St);
    cudaGetSymbolAddress((void**)&xh,   g_xh);
    cudaGetSymbolAddress((void**)&xl,   g_xl);
    cudaGetSymbolAddress((void**)&yh,   g_yh);
    cudaGetSymbolAddress((void**)&yl,   g_yl);
    cudaGetSymbolAddress((void**)&Eth,  g_Eth);
    cudaGetSymbolAddress((void**)&Etl,  g_Etl);
    cudaGetSymbolAddress((void**)&xsth, g_xsth);
    cudaGetSymbolAddress((void**)&xstl, g_xstl);

    init_stats_kernel<<<(BATCH * MDIM + 255) / 256, 256>>>();

    const size_t nx = (size_t)BATCH * MDIM * DDIM;   // 16.7M elems each of x,y
    split_kernel<<<(unsigned)(nx / 1024), 256>>>(x, xh, xl);
    split_kernel<<<(unsigned)(nx / 1024), 256>>>(y, yh, yl);

    // GEMM1: St[n][m] = sum_d y[n,d]*x[m,d]; A=y rows n, B=x rows m, K=D
    {
        dim3 grid(MDIM / 128, NDIM / 128, BATCH);
        gemm_bf16x3<<<grid, 256, GEMM_SMEM>>>(
            yh, yl, xh, xl, St,
            DDIM, (size_t)NDIM * DDIM, (size_t)MDIM * DDIM,
            (size_t)NDIM * MDIM, MDIM);
    }
    {
        dim3 grid(MDIM / 256, NDIM / 128, BATCH);
        colmax_kernel<<<grid, 256>>>();
        exp_kernel<<<grid, 256>>>();
    }
    xst_kernel<<<dim3(DDIM / 32, MDIM / 32, BATCH), 256>>>(x);

    // GEMM2: out[n][d] = sum_m Et[n,m]*xst[d,m]; A=Et rows n, B=xst rows d, K=M
    {
        dim3 grid(DDIM / 128, NDIM / 128, BATCH);
        gemm_bf16x3<<<grid, 256, GEMM_SMEM>>>(
            Eth, Etl, xsth, xstl, out,
            MDIM, (size_t)NDIM * MDIM, (size_t)DDIM * MDIM,
            (size_t)NDIM * DDIM, DDIM);
    }
}